// round 17
// baseline (speedup 1.0000x reference)
#include <cuda_runtime.h>
#include <cuda_fp16.h>
#include <math.h>

#define BATCH 8
#define T 2048
#define C 1024
#define H 64

// Scratch: projected k (row-major fp16), v (TRANSPOSED fp16 [b][h][t]), partials.
__device__ __half g_k2[BATCH * T * H];
__device__ __half g_vT[BATCH * H * T];
#define NCHUNK 4
#define CHUNK_TILES 8
__device__ float g_po[BATCH * NCHUNK * T * H];
__device__ float g_pm[BATCH * T * NCHUNK];
__device__ float g_pl[BATCH * T * NCHUNK];

__device__ __forceinline__ void mma_f16(float* d, const unsigned* a,
                                        unsigned b0, unsigned b1) {
    asm volatile(
        "mma.sync.aligned.m16n8k16.row.col.f32.f16.f16.f32 "
        "{%0,%1,%2,%3}, {%4,%5,%6,%7}, {%8,%9}, {%0,%1,%2,%3};"
        : "+f"(d[0]), "+f"(d[1]), "+f"(d[2]), "+f"(d[3])
        : "r"(a[0]), "r"(a[1]), "r"(a[2]), "r"(a[3]), "r"(b0), "r"(b1));
}

__device__ __forceinline__ unsigned h2u(float x, float y) {
    __half2 h = __floats2half2_rn(x, y);
    return *reinterpret_cast<unsigned*>(&h);
}

__device__ __forceinline__ unsigned smem_u32(const void* p) {
    return (unsigned)__cvta_generic_to_shared(p);
}
__device__ __forceinline__ void cp16(unsigned dst, const void* src) {
    asm volatile("cp.async.ca.shared.global [%0], [%1], 16;" :: "r"(dst), "l"(src));
}
__device__ __forceinline__ void cp_commit() { asm volatile("cp.async.commit_group;"); }
__device__ __forceinline__ void cp_wait0() { asm volatile("cp.async.wait_group 0;"); }

// ---------------------------------------------------------------------------
// Projection (fp16 mma): BM=128, BN=128, BK=32, 512 threads (16 warps, 4x4
// warp grid, warp tile 32x32). Double-buffered smem, rows padded to 40 halves.
// Outputs: g_k2 row-major fp16; g_vT transposed fp16.
// ---------------------------------------------------------------------------
#define PBM 128
#define PBK 32
#define KP32 20                       // u32 per smem row (40 halves)
#define TILE_W (128 * KP32)           // u32 per A or B tile
#define PROJ_SMEM (4 * TILE_W * 4)    // 2 buffers x (A+B) = 40 KB

__global__ void __launch_bounds__(512) proj_kernel(const float* __restrict__ x,
                                                   const float* __restrict__ Wk,
                                                   const float* __restrict__ Wv) {
    extern __shared__ unsigned psm[];
    unsigned* Ab = psm;                // 2 x TILE_W
    unsigned* Bb = psm + 2 * TILE_W;   // 2 x TILE_W

    const int tid = threadIdx.x;
    const int wid = tid >> 5;
    const int lane = tid & 31;
    const int g = lane >> 2;
    const int t = lane & 3;
    const int wr = wid >> 2;           // 0..3 : 32-row strip
    const int wc = wid & 3;            // 0..3 : 32-col strip
    const int m0 = blockIdx.x * PBM;

    // Staging: A/B tiles are 128 rows x 32 f32 = 1024 float4 each; 2 per thread.
    const int ar = tid >> 3;           // 0..63 (rows ar, ar+64)
    const int ac = (tid & 7) * 4;      // f32 col 0..28
    const int au = ac >> 1;            // u32 col in smem row

    // B rows: l=0 -> Wk row ar, l=1 -> Wv row ar (rows 64..127 are Wv)
    const float* bsrc[2] = { Wk + (size_t)ar * C, Wv + (size_t)ar * C };

    float4 pa[2], pb[2];
#pragma unroll
    for (int l = 0; l < 2; l++) {
        pa[l] = *reinterpret_cast<const float4*>(x + (size_t)(m0 + ar + 64 * l) * C + ac);
        pb[l] = *reinterpret_cast<const float4*>(bsrc[l] + ac);
    }

    auto stage = [&](unsigned* As, unsigned* Bs) {
#pragma unroll
        for (int l = 0; l < 2; l++) {
            int row = ar + 64 * l;
            uint2 av = make_uint2(h2u(pa[l].x, pa[l].y), h2u(pa[l].z, pa[l].w));
            uint2 bv = make_uint2(h2u(pb[l].x, pb[l].y), h2u(pb[l].z, pb[l].w));
            *reinterpret_cast<uint2*>(As + row * KP32 + au) = av;
            *reinterpret_cast<uint2*>(Bs + row * KP32 + au) = bv;
        }
    };

    stage(Ab, Bb);

    float acc[2][4][4];
#pragma unroll
    for (int mf = 0; mf < 2; mf++)
#pragma unroll
        for (int nf = 0; nf < 4; nf++)
#pragma unroll
            for (int e = 0; e < 4; e++) acc[mf][nf][e] = 0.f;

    const int NT = C / PBK;  // 32
    for (int i = 0; i < NT; i++) {
        __syncthreads();
        const int cur = i & 1;
        unsigned* As = Ab + cur * TILE_W;
        unsigned* Bs = Bb + cur * TILE_W;

        if (i + 1 < NT) {
            const int k0n = (i + 1) * PBK;
#pragma unroll
            for (int l = 0; l < 2; l++) {
                pa[l] = *reinterpret_cast<const float4*>(x + (size_t)(m0 + ar + 64 * l) * C + k0n + ac);
                pb[l] = *reinterpret_cast<const float4*>(bsrc[l] + k0n + ac);
            }
        }

#pragma unroll
        for (int ks = 0; ks < 2; ks++) {
            const int ku = ks * 8;    // u32 offset (16 halves)
            unsigned a[2][4];
#pragma unroll
            for (int mf = 0; mf < 2; mf++) {
                const int r = wr * 32 + mf * 16 + g;
                a[mf][0] = As[r * KP32 + ku + t];
                a[mf][1] = As[(r + 8) * KP32 + ku + t];
                a[mf][2] = As[r * KP32 + ku + t + 4];
                a[mf][3] = As[(r + 8) * KP32 + ku + t + 4];
            }
#pragma unroll
            for (int nf = 0; nf < 4; nf++) {
                const int n = wc * 32 + nf * 8 + g;
                unsigned b0 = Bs[n * KP32 + ku + t];
                unsigned b1 = Bs[n * KP32 + ku + t + 4];
#pragma unroll
                for (int mf = 0; mf < 2; mf++)
                    mma_f16(acc[mf][nf], a[mf], b0, b1);
            }
        }

        if (i + 1 < NT)
            stage(Ab + ((i + 1) & 1) * TILE_W, Bb + ((i + 1) & 1) * TILE_W);
    }

    // Epilogue: warps wc 0,1 -> k (cols 0..63, row-major); wc 2,3 -> v (transposed)
    const int bidx = m0 >> 11;
    const int tr0 = m0 & 2047;
    if (wc < 2) {
#pragma unroll
        for (int mf = 0; mf < 2; mf++) {
            const int r0 = m0 + wr * 32 + mf * 16;
#pragma unroll
            for (int nf = 0; nf < 4; nf++) {
                int col = wc * 32 + nf * 8 + 2 * t;
                *reinterpret_cast<unsigned*>(&g_k2[(size_t)(r0 + g) * H + col]) =
                    h2u(acc[mf][nf][0], acc[mf][nf][1]);
                *reinterpret_cast<unsigned*>(&g_k2[(size_t)(r0 + g + 8) * H + col]) =
                    h2u(acc[mf][nf][2], acc[mf][nf][3]);
            }
        }
    } else {
        __half* vb = g_vT + (size_t)bidx * H * T;
#pragma unroll
        for (int mf = 0; mf < 2; mf++) {
            const int r = tr0 + wr * 32 + mf * 16 + g;
#pragma unroll
            for (int nf = 0; nf < 4; nf++) {
                int col = (wc - 2) * 32 + nf * 8 + 2 * t;
                vb[(size_t)col * T + r]            = __float2half_rn(acc[mf][nf][0]);
                vb[(size_t)(col + 1) * T + r]      = __float2half_rn(acc[mf][nf][1]);
                vb[(size_t)col * T + r + 8]        = __float2half_rn(acc[mf][nf][2]);
                vb[(size_t)(col + 1) * T + r + 8]  = __float2half_rn(acc[mf][nf][3]);
            }
        }
    }
}

// ---------------------------------------------------------------------------
// Attention pass 1 (fp16 mma): split-KV, cp.async double-buffered K and Vt.
// BQ=64 (4 warps x 16 rows), BK=64. Smem rows = 72 halves (36 u32).
// ---------------------------------------------------------------------------
#define BQ 64
#define BK 64
#define KS32 36
#define KVW (64 * KS32 * 2)
#define PS_W (16 * KS32)
#define ATTN_SMEM ((2 * KVW + 4 * PS_W) * 4)   // 46080 B
#define LOG2E 1.4426950408889634f

__global__ void __launch_bounds__(128) attn_chunk_kernel() {
    const int qt = 31 - (int)blockIdx.x;   // heavy-first
    const int chunk = blockIdx.y;
    if (chunk * CHUNK_TILES > qt) return;
    const int b = blockIdx.z;

    extern __shared__ unsigned char smraw[];
    unsigned* KVb = reinterpret_cast<unsigned*>(smraw);
    unsigned* PsAll = KVb + 2 * KVW;

    const int tid = threadIdx.x;
    const int wid = tid >> 5;
    const int lane = tid & 31;
    const int g = lane >> 2;
    const int t = lane & 3;
    const int q0 = qt * BQ;

    unsigned* Psw = PsAll + wid * PS_W;
    const __half* kb = g_k2 + (size_t)b * T * H;
    const __half* vTb = g_vT + (size_t)b * H * T;

    const int kt0 = chunk * CHUNK_TILES;
    const int ktend = min(qt, kt0 + CHUNK_TILES - 1);
    const int niter = ktend - kt0 + 1;

    const int qra = q0 + wid * 16 + g;
    const int qrb = qra + 8;
    unsigned qa[4][4];
#pragma unroll
    for (int kf = 0; kf < 4; kf++) {
        qa[kf][0] = *reinterpret_cast<const unsigned*>(kb + (size_t)qra * H + kf * 16 + 2 * t);
        qa[kf][1] = *reinterpret_cast<const unsigned*>(kb + (size_t)qrb * H + kf * 16 + 2 * t);
        qa[kf][2] = *reinterpret_cast<const unsigned*>(kb + (size_t)qra * H + kf * 16 + 2 * t + 8);
        qa[kf][3] = *reinterpret_cast<const unsigned*>(kb + (size_t)qrb * H + kf * 16 + 2 * t + 8);
    }

    const int crow = tid >> 3;
    const int cseg = tid & 7;

    auto issue_copy = [&](int kvt, int buf) {
        unsigned* Ks = KVb + buf * KVW;
        unsigned* Vs = Ks + 64 * KS32;
        const int j0g = kvt * BK;
#pragma unroll
        for (int l = 0; l < 4; l++) {
            int row = crow + l * 16;
            cp16(smem_u32(Ks + row * KS32 + cseg * 4),
                 kb + (size_t)(j0g + row) * H + cseg * 8);
            cp16(smem_u32(Vs + row * KS32 + cseg * 4),
                 vTb + (size_t)row * T + j0g + cseg * 8);
        }
        cp_commit();
    };

    issue_copy(kt0, 0);

    float o[8][4];
#pragma unroll
    for (int nf = 0; nf < 8; nf++)
#pragma unroll
        for (int e = 0; e < 4; e++) o[nf][e] = 0.f;
    float m_i[2] = {-INFINITY, -INFINITY};
    float l_i[2] = {0.f, 0.f};

    const float S2 = 0.125f * LOG2E;

    for (int it = 0; it < niter; it++) {
        const int kvt = kt0 + it;
        const int j0g = kvt * BK;
        const int cur = it & 1;
        unsigned* Ks = KVb + cur * KVW;
        unsigned* Vs = Ks + 64 * KS32;

        cp_wait0();
        __syncthreads();

        if (it + 1 < niter) issue_copy(kvt + 1, cur ^ 1);

        float s[8][4];
#pragma unroll
        for (int nf = 0; nf < 8; nf++)
#pragma unroll
            for (int e = 0; e < 4; e++) s[nf][e] = 0.f;
#pragma unroll
        for (int kf = 0; kf < 4; kf++) {
            const int ku = kf * 8;
#pragma unroll
            for (int nf = 0; nf < 8; nf++) {
                unsigned b0 = Ks[(nf * 8 + g) * KS32 + ku + t];
                unsigned b1 = Ks[(nf * 8 + g) * KS32 + ku + t + 4];
                mma_f16(s[nf], qa[kf], b0, b1);
            }
        }

        const bool needm = (kvt == qt);
#pragma unroll
        for (int nf = 0; nf < 8; nf++)
#pragma unroll
            for (int e = 0; e < 4; e++) {
                int col = j0g + nf * 8 + 2 * t + (e & 1);
                int row = (e & 2) ? qrb : qra;
                float v = s[nf][e] * S2;
                if (needm && col > row) v = -INFINITY;
                s[nf][e] = v;
            }

#pragma unroll
        for (int h2 = 0; h2 < 2; h2++) {
            const int e0 = h2 * 2;
            float rm = -INFINITY;
#pragma unroll
            for (int nf = 0; nf < 8; nf++)
                rm = fmaxf(rm, fmaxf(s[nf][e0], s[nf][e0 + 1]));
            rm = fmaxf(rm, __shfl_xor_sync(0xFFFFFFFFu, rm, 1));
            rm = fmaxf(rm, __shfl_xor_sync(0xFFFFFFFFu, rm, 2));
            float mn = fmaxf(m_i[h2], rm);
            float al = exp2f(m_i[h2] - mn);
            float ps = 0.f;
#pragma unroll
            for (int nf = 0; nf < 8; nf++) {
                float p0 = exp2f(s[nf][e0] - mn);
                float p1 = exp2f(s[nf][e0 + 1] - mn);
                ps += p0 + p1;
                o[nf][e0] *= al;
                o[nf][e0 + 1] *= al;
                Psw[(g + 8 * h2) * KS32 + nf * 4 + t] = h2u(p0, p1);
            }
            ps += __shfl_xor_sync(0xFFFFFFFFu, ps, 1);
            ps += __shfl_xor_sync(0xFFFFFFFFu, ps, 2);
            l_i[h2] = l_i[h2] * al + ps;
            m_i[h2] = mn;
        }
        __syncwarp();

#pragma unroll
        for (int kf = 0; kf < 4; kf++) {
            const int ku = kf * 8;
            unsigned a[4];
            a[0] = Psw[g * KS32 + ku + t];
            a[1] = Psw[(g + 8) * KS32 + ku + t];
            a[2] = Psw[g * KS32 + ku + t + 4];
            a[3] = Psw[(g + 8) * KS32 + ku + t + 4];
#pragma unroll
            for (int nf = 0; nf < 8; nf++) {
                unsigned b0 = Vs[(nf * 8 + g) * KS32 + ku + t];
                unsigned b1 = Vs[(nf * 8 + g) * KS32 + ku + t + 4];
                mma_f16(o[nf], a, b0, b1);
            }
        }
    }

    float* po = g_po + ((size_t)(b * NCHUNK + chunk) * T) * H;
#pragma unroll
    for (int nf = 0; nf < 8; nf++) {
        int col = nf * 8 + 2 * t;
        *reinterpret_cast<float2*>(po + (size_t)qra * H + col) = make_float2(o[nf][0], o[nf][1]);
        *reinterpret_cast<float2*>(po + (size_t)qrb * H + col) = make_float2(o[nf][2], o[nf][3]);
    }
    if (t == 0) {
        g_pm[((size_t)b * T + qra) * NCHUNK + chunk] = m_i[0];
        g_pl[((size_t)b * T + qra) * NCHUNK + chunk] = l_i[0];
        g_pm[((size_t)b * T + qrb) * NCHUNK + chunk] = m_i[1];
        g_pl[((size_t)b * T + qrb) * NCHUNK + chunk] = l_i[1];
    }
}

// ---------------------------------------------------------------------------
// Pass 2: combine partials.
// ---------------------------------------------------------------------------
__global__ void __launch_bounds__(256) combine_kernel(float* __restrict__ out) {
    const int wid = threadIdx.x >> 5;
    const int lane = threadIdx.x & 31;
    const int row = blockIdx.x * 8 + wid;
    const int b = row >> 11;
    const int trow = row & 2047;
    const int qt = trow >> 6;
    const int nch = qt / CHUNK_TILES + 1;
    const int col = lane * 2;

    float m2[NCHUNK], lv[NCHUNK];
    float M2 = -INFINITY;
#pragma unroll
    for (int c = 0; c < NCHUNK; c++) {
        if (c < nch) {
            m2[c] = g_pm[((size_t)b * T + trow) * NCHUNK + c];
            lv[c] = g_pl[((size_t)b * T + trow) * NCHUNK + c];
            M2 = fmaxf(M2, m2[c]);
        }
    }
    float denom = 0.f;
    float acc0 = 0.f, acc1 = 0.f;
#pragma unroll
    for (int c = 0; c < NCHUNK; c++) {
        if (c < nch) {
            float w = exp2f(m2[c] - M2);
            denom += w * lv[c];
            float2 v = *reinterpret_cast<const float2*>(
                g_po + (((size_t)(b * NCHUNK + c) * T + trow)) * H + col);
            acc0 += w * v.x;
            acc1 += w * v.y;
        }
    }
    float inv = 1.f / denom;
    *reinterpret_cast<float2*>(out + ((size_t)b * T + trow) * H + col) =
        make_float2(acc0 * inv, acc1 * inv);
}

extern "C" void kernel_launch(void* const* d_in, const int* in_sizes, int n_in,
                              void* d_out, int out_size) {
    const float* x  = (const float*)d_in[0];
    const float* Wk = (const float*)d_in[1];
    const float* Wv = (const float*)d_in[2];
    float* out = (float*)d_out;

    cudaFuncSetAttribute(proj_kernel, cudaFuncAttributeMaxDynamicSharedMemorySize, PROJ_SMEM);
    cudaFuncSetAttribute(attn_chunk_kernel, cudaFuncAttributeMaxDynamicSharedMemorySize, ATTN_SMEM);

    proj_kernel<<<(BATCH * T) / PBM, 512, PROJ_SMEM>>>(x, Wk, Wv);
    attn_chunk_kernel<<<dim3(T / BQ, NCHUNK, BATCH), 128, ATTN_SMEM>>>();
    combine_kernel<<<(BATCH * T) / 8, 256>>>(out);
}